// round 4
// baseline (speedup 1.0000x reference)
#include <cuda_runtime.h>
#include <cuda_bf16.h>
#include <cstdint>

// Problem constants (fixed by the reference)
#define TT 4096      // T
#define NH 16        // H
#define NC 64        // number of chunks (T / CHUNK)
// B=2, D=128, CHUNK=64, HID=2048, K3 = 3*2048 = 6144 (bf16x3 split-K)

// ---------------------------------------------------------------------------
// Scratch (device globals; no allocation allowed anywhere)
// ---------------------------------------------------------------------------
// g_qkv: [8192, 6144] qkv projection output. After qkv_post consumes it:
//   [0, 8192*2048)          -> og (normed+gated o, dense-GEMM input)
//   [8192*2048, 2*8192*2048)-> gate (sigmoid(hs @ w_g^T))
__device__ float g_qkv[50331648];            // 8192*6144
__device__ float g_q[16777216];              // [B,H,T,D] = 32*4096*128
__device__ float g_k[16777216];
__device__ float g_v[16777216];
__device__ float g_U[33554432];              // [B,H,NC,128,128] decayed K^T V per chunk
__device__ float g_S[33554432];              // [B,H,NC,128,128] state entering each chunk
__device__ float g_o[16777216];              // [B,H,T,D] attention output
// bf16x3 operands: A' = [hi | lo | hi] (K'=6144), B' = [hi | hi | lo]
__device__ __nv_bfloat16 g_A[50331648];      // [8192, 6144]
__device__ __nv_bfloat16 g_B[62914560];      // [10240, 6144]: wqkv(6144) | wg(2048) | wd(2048)

// slope_h = -2^{-(h+1)/2} * (1 - 11/31 + 1e-5)   (LAYER_IDX=12, N_LAYERS=32, H=16)
__device__ __forceinline__ float head_slope(int h) {
    const float scale = 1.0f - 11.0f / 31.0f + 1e-5f;
    return -exp2f(-0.5f * (float)(h + 1)) * scale;
}

// ---------------------------------------------------------------------------
// bf16x3 split: in [rows,2048] fp32 -> out [rows,6144] bf16.
// bmode=0 (A side): segments {hi, lo, hi};  bmode=1 (B side): {hi, hi, lo}.
// n4 = rows*512 (one float4 per thread).
// ---------------------------------------------------------------------------
union Pack4 { __nv_bfloat16 b[4]; uint2 u; };

__global__ __launch_bounds__(256) void split_k(const float* __restrict__ in,
                                               __nv_bfloat16* __restrict__ out,
                                               int n4, int bmode) {
    int idx = blockIdx.x * 256 + threadIdx.x;
    if (idx >= n4) return;
    int r = idx >> 9, k4 = (idx & 511) << 2;
    float4 x = *(const float4*)(in + (size_t)r * 2048 + k4);
    float xs[4] = {x.x, x.y, x.z, x.w};
    Pack4 H, L;
#pragma unroll
    for (int j = 0; j < 4; j++) {
        __nv_bfloat16 h = __float2bfloat16(xs[j]);
        H.b[j] = h;
        L.b[j] = __float2bfloat16(xs[j] - __bfloat162float(h));
    }
    size_t base = (size_t)r * 6144 + k4;
    *(uint2*)(out + base) = H.u;
    if (bmode) {
        *(uint2*)(out + base + 2048) = H.u;
        *(uint2*)(out + base + 4096) = L.u;
    } else {
        *(uint2*)(out + base + 2048) = L.u;
        *(uint2*)(out + base + 4096) = H.u;
    }
}

// ---------------------------------------------------------------------------
// bf16 NT tensor-core GEMM: C[M,N] = A'[M,6144] * B'[N,6144]^T, fp32 accum.
// 128x128 CTA tile, 256 threads = 8 warps (2x4), warp tile 64x32,
// mma.sync.m16n8k16. Double-buffered smem (padded rows, conflict-free).
// ACT==1 -> sigmoid epilogue.
// ---------------------------------------------------------------------------
#define K3 6144

__device__ __forceinline__ void mma16816(float* c, const uint32_t* a, const uint32_t* b) {
    asm volatile(
        "mma.sync.aligned.m16n8k16.row.col.f32.bf16.bf16.f32 "
        "{%0,%1,%2,%3}, {%4,%5,%6,%7}, {%8,%9}, {%0,%1,%2,%3};"
        : "+f"(c[0]), "+f"(c[1]), "+f"(c[2]), "+f"(c[3])
        : "r"(a[0]), "r"(a[1]), "r"(a[2]), "r"(a[3]), "r"(b[0]), "r"(b[1]));
}

template <int N, int ACT>
__global__ __launch_bounds__(256) void mma_gemm(const __nv_bfloat16* __restrict__ A,
                                                const __nv_bfloat16* __restrict__ B,
                                                float* __restrict__ C) {
    __shared__ __nv_bfloat16 As[2][128][40];   // 32-wide K slab + 8 pad
    __shared__ __nv_bfloat16 Bs[2][128][40];
    const int tid = threadIdx.x;
    const int m0 = blockIdx.y * 128, n0 = blockIdx.x * 128;
    const int lrow = tid >> 1, lseg = (tid & 1) * 16;
    const __nv_bfloat16* Ag = A + (size_t)(m0 + lrow) * K3 + lseg;
    const __nv_bfloat16* Bg = B + (size_t)(n0 + lrow) * K3 + lseg;

    const int wid = tid >> 5, lane = tid & 31;
    const int wm = wid >> 2, wn = wid & 3;
    const int grp = lane >> 2, qd = lane & 3;
    const int mbase = wm * 64, nbase = wn * 32;

    float acc[4][4][4];
#pragma unroll
    for (int mt = 0; mt < 4; mt++)
#pragma unroll
        for (int nt = 0; nt < 4; nt++)
#pragma unroll
            for (int j = 0; j < 4; j++) acc[mt][nt][j] = 0.f;

    // preload slab 0
    {
        uint4 a0 = *(const uint4*)(Ag);
        uint4 a1 = *(const uint4*)(Ag + 8);
        uint4 b0 = *(const uint4*)(Bg);
        uint4 b1 = *(const uint4*)(Bg + 8);
        *(uint4*)&As[0][lrow][lseg]     = a0;
        *(uint4*)&As[0][lrow][lseg + 8] = a1;
        *(uint4*)&Bs[0][lrow][lseg]     = b0;
        *(uint4*)&Bs[0][lrow][lseg + 8] = b1;
    }
    __syncthreads();

    int buf = 0;
    for (int kt = 32; kt <= K3; kt += 32) {
        const bool more = (kt < K3);
        uint4 na0, na1, nb0, nb1;
        if (more) {
            na0 = *(const uint4*)(Ag + kt);
            na1 = *(const uint4*)(Ag + kt + 8);
            nb0 = *(const uint4*)(Bg + kt);
            nb1 = *(const uint4*)(Bg + kt + 8);
        }

        // compute on current buffer: two k16 steps
#pragma unroll
        for (int kk = 0; kk < 32; kk += 16) {
            uint32_t au[4][4], bu[4][2];
#pragma unroll
            for (int mt = 0; mt < 4; mt++) {
                int row = mbase + mt * 16 + grp;
                au[mt][0] = *(const uint32_t*)&As[buf][row][kk + qd * 2];
                au[mt][1] = *(const uint32_t*)&As[buf][row + 8][kk + qd * 2];
                au[mt][2] = *(const uint32_t*)&As[buf][row][kk + 8 + qd * 2];
                au[mt][3] = *(const uint32_t*)&As[buf][row + 8][kk + 8 + qd * 2];
            }
#pragma unroll
            for (int nt = 0; nt < 4; nt++) {
                int col = nbase + nt * 8 + grp;
                bu[nt][0] = *(const uint32_t*)&Bs[buf][col][kk + qd * 2];
                bu[nt][1] = *(const uint32_t*)&Bs[buf][col][kk + 8 + qd * 2];
            }
#pragma unroll
            for (int mt = 0; mt < 4; mt++)
#pragma unroll
                for (int nt = 0; nt < 4; nt++)
                    mma16816(acc[mt][nt], au[mt], bu[nt]);
        }

        if (more) {
            buf ^= 1;
            *(uint4*)&As[buf][lrow][lseg]     = na0;
            *(uint4*)&As[buf][lrow][lseg + 8] = na1;
            *(uint4*)&Bs[buf][lrow][lseg]     = nb0;
            *(uint4*)&Bs[buf][lrow][lseg + 8] = nb1;
            __syncthreads();
        }
    }

    // epilogue
#pragma unroll
    for (int mt = 0; mt < 4; mt++) {
#pragma unroll
        for (int nt = 0; nt < 4; nt++) {
            int row = m0 + mbase + mt * 16 + grp;
            int col = n0 + nbase + nt * 8 + qd * 2;
            float v0 = acc[mt][nt][0], v1 = acc[mt][nt][1];
            float v2 = acc[mt][nt][2], v3 = acc[mt][nt][3];
            if (ACT == 1) {
                v0 = 1.f / (1.f + expf(-v0));
                v1 = 1.f / (1.f + expf(-v1));
                v2 = 1.f / (1.f + expf(-v2));
                v3 = 1.f / (1.f + expf(-v3));
            }
            *(float2*)&C[(size_t)row * N + col]       = make_float2(v0, v1);
            *(float2*)&C[(size_t)(row + 8) * N + col] = make_float2(v2, v3);
        }
    }
}

// ---------------------------------------------------------------------------
// QKV post-process: per-(b,t,h) rmsnorm on q,k (D=128), RoPE on first 64 dims,
// fold D^-0.5 into q, scatter q/k/v to [B,H,T,D].  grid = (B*T, H), block 128
// ---------------------------------------------------------------------------
__global__ __launch_bounds__(128) void qkv_post_k(const int* __restrict__ pos_ids,
                                                  const float* __restrict__ qw,
                                                  const float* __restrict__ kw) {
    const int bt = blockIdx.x, h = blockIdx.y, d = threadIdx.x;
    const int b = bt >> 12, t = bt & 4095;
    const float* base = g_qkv + (size_t)bt * 6144 + h * 128 + d;
    float qv = base[0];
    float kv = base[2048];
    float vv = base[4096];

    float sq = qv * qv, sk = kv * kv;
#pragma unroll
    for (int o = 16; o; o >>= 1) {
        sq += __shfl_xor_sync(0xffffffffu, sq, o);
        sk += __shfl_xor_sync(0xffffffffu, sk, o);
    }
    __shared__ float rq[4], rk[4];
    if ((d & 31) == 0) { rq[d >> 5] = sq; rk[d >> 5] = sk; }
    __syncthreads();
    float ssq = rq[0] + rq[1] + rq[2] + rq[3];
    float ssk = rk[0] + rk[1] + rk[2] + rk[3];
    float qn = qw[d] * (qv * rsqrtf(ssq * (1.f / 128.f) + 1e-6f));
    float kn = kw[d] * (kv * rsqrtf(ssk * (1.f / 128.f) + 1e-6f));

    __shared__ float bq[128], bk[128];
    bq[d] = qn; bk[d] = kn;
    __syncthreads();
    if (d < 64) {
        int i = d & 31;
        float inv = exp2f((float)(2 * i) * (-13.287712379549449f / 64.f));
        float ang = (float)pos_ids[bt] * inv;
        float cs, sn;
        sincosf(ang, &sn, &cs);
        if (d < 32) { qn = qn * cs - bq[d + 32] * sn; kn = kn * cs - bk[d + 32] * sn; }
        else        { qn = qn * cs + bq[d - 32] * sn; kn = kn * cs + bk[d - 32] * sn; }
    }
    const size_t oi = ((size_t)(b * NH + h) * TT + t) * 128 + d;
    g_q[oi] = qn * 0.08838834764831845f;  // D^-0.5 folded into q
    g_k[oi] = kn;
    g_v[oi] = vv;
}

// ---------------------------------------------------------------------------
// U_c[e,d] = sum_i exp(slope*(63-i)) * K[c,i,e] * V[c,i,d]   (128x128, K=64)
// grid = (NC, B*H), 256 threads, 8x8 per-thread tile. 64KB dynamic smem.
// ---------------------------------------------------------------------------
__global__ __launch_bounds__(256) void chunk_kv_k() {
    extern __shared__ float sm[];
    float* Ks = sm;               // 64*128
    float* Vs = sm + 8192;        // 64*128
    float* kd = sm + 16384;       // 64
    const int c = blockIdx.x, bh = blockIdx.y;
    const float slope = head_slope(bh & 15);
    const int tid = threadIdx.x, tx = tid & 15, ty = tid >> 4;
    const float* kg = g_k + ((size_t)bh * TT + c * 64) * 128;
    const float* vg = g_v + ((size_t)bh * TT + c * 64) * 128;
    for (int t0 = tid * 4; t0 < 8192; t0 += 1024) {
        *(float4*)(Ks + t0) = *(const float4*)(kg + t0);
        *(float4*)(Vs + t0) = *(const float4*)(vg + t0);
    }
    if (tid < 64) kd[tid] = expf(slope * (float)(63 - tid));
    __syncthreads();

    float acc[8][8];
#pragma unroll
    for (int r = 0; r < 8; r++)
#pragma unroll
        for (int cc = 0; cc < 8; cc++) acc[r][cc] = 0.f;

    for (int i = 0; i < 64; i++) {
        float w = kd[i];
        float4 a0 = *(const float4*)(Ks + i * 128 + ty * 8);
        float4 a1 = *(const float4*)(Ks + i * 128 + ty * 8 + 4);
        float4 b0 = *(const float4*)(Vs + i * 128 + tx * 8);
        float4 b1 = *(const float4*)(Vs + i * 128 + tx * 8 + 4);
        float ar[8] = {a0.x * w, a0.y * w, a0.z * w, a0.w * w,
                       a1.x * w, a1.y * w, a1.z * w, a1.w * w};
        float br[8] = {b0.x, b0.y, b0.z, b0.w, b1.x, b1.y, b1.z, b1.w};
#pragma unroll
        for (int r = 0; r < 8; r++)
#pragma unroll
            for (int cc = 0; cc < 8; cc++) acc[r][cc] += ar[r] * br[cc];
    }

    float* Ug = g_U + ((size_t)bh * NC + c) * 16384;
#pragma unroll
    for (int r = 0; r < 8; r++) {
        float* p = Ug + (ty * 8 + r) * 128 + tx * 8;
        *(float4*)p       = make_float4(acc[r][0], acc[r][1], acc[r][2], acc[r][3]);
        *(float4*)(p + 4) = make_float4(acc[r][4], acc[r][5], acc[r][6], acc[r][7]);
    }
}

// ---------------------------------------------------------------------------
// Prefix scan over chunks: S[0]=0; S[c] = lam*S[c-1] + U[c-1], lam = e^{slope*64}
// grid = (B*H, 8 parts of the 128x128 plane), 256 threads, 8 elems/thread.
// ---------------------------------------------------------------------------
__global__ __launch_bounds__(256) void scan_k() {
    const int bh = blockIdx.x, part = blockIdx.y;
    const float lam = expf(head_slope(bh & 15) * 64.f);
    const int e0 = part * 2048 + threadIdx.x;
    float s[8];
#pragma unroll
    for (int j = 0; j < 8; j++) s[j] = 0.f;
    float* Sb = g_S + (size_t)bh * NC * 16384;
    const float* Ub = g_U + (size_t)bh * NC * 16384;
#pragma unroll
    for (int j = 0; j < 8; j++) Sb[e0 + j * 256] = 0.f;
    for (int c = 1; c < NC; c++) {
        const float* u = Ub + (size_t)(c - 1) * 16384;
        float* so = Sb + (size_t)c * 16384;
#pragma unroll
        for (int j = 0; j < 8; j++) {
            s[j] = lam * s[j] + u[e0 + j * 256];
            so[e0 + j * 256] = s[j];
        }
    }
}

// ---------------------------------------------------------------------------
// Chunk output: o = mask(Q K^T) V + qdec * (Q @ S_c)     (64x128 per block)
// grid = (NC, B*H), 256 threads (16x16), ~89KB dynamic smem.
// ---------------------------------------------------------------------------
__global__ __launch_bounds__(256) void chunk_out_k() {
    extern __shared__ float sm[];
    float* sQ   = sm;                    // 64*129
    float* sKV  = sm + 64 * 129;         // 64*129 (K, then V)
    float* sAtt = sm + 2 * 64 * 129;     // 64*65
    float* sS   = sAtt + 64 * 65;        // 16*128
    float* sEi  = sS + 16 * 128;         // 65 : e^{slope*t}, t=0..64
    const int c = blockIdx.x, bh = blockIdx.y;
    const float slope = head_slope(bh & 15);
    const int tid = threadIdx.x, tx = tid & 15, ty = tid >> 4;
    const float* qg = g_q + ((size_t)bh * TT + c * 64) * 128;
    const float* kg = g_k + ((size_t)bh * TT + c * 64) * 128;
    const float* vg = g_v + ((size_t)bh * TT + c * 64) * 128;

    for (int t0 = tid; t0 < 8192; t0 += 256) {
        int r = t0 >> 7, cc = t0 & 127;
        sQ[r * 129 + cc]  = qg[t0];
        sKV[r * 129 + cc] = kg[t0];
    }
    if (tid < 65) sEi[tid] = expf(slope * (float)tid);
    __syncthreads();

    float att[4][4];
#pragma unroll
    for (int r = 0; r < 4; r++)
#pragma unroll
        for (int cc = 0; cc < 4; cc++) att[r][cc] = 0.f;
    for (int d = 0; d < 128; d++) {
        float qv[4], kv[4];
#pragma unroll
        for (int r = 0; r < 4; r++) qv[r] = sQ[(ty + 16 * r) * 129 + d];
#pragma unroll
        for (int cc = 0; cc < 4; cc++) kv[cc] = sKV[(tx + 16 * cc) * 129 + d];
#pragma unroll
        for (int r = 0; r < 4; r++)
#pragma unroll
            for (int cc = 0; cc < 4; cc++) att[r][cc] += qv[r] * kv[cc];
    }
#pragma unroll
    for (int r = 0; r < 4; r++) {
        int i = ty + 16 * r;
#pragma unroll
        for (int cc = 0; cc < 4; cc++) {
            int j = tx + 16 * cc;
            sAtt[i * 65 + j] = (i >= j) ? att[r][cc] * sEi[i - j] : 0.f;
        }
    }
    __syncthreads();

    for (int t0 = tid; t0 < 8192; t0 += 256) {
        int r = t0 >> 7, cc = t0 & 127;
        sKV[r * 129 + cc] = vg[t0];
    }
    __syncthreads();

    float oA[4][8], oB[4][8];
#pragma unroll
    for (int r = 0; r < 4; r++)
#pragma unroll
        for (int cc = 0; cc < 8; cc++) { oA[r][cc] = 0.f; oB[r][cc] = 0.f; }

    for (int j = 0; j < 64; j++) {
        float av[4], bv[8];
#pragma unroll
        for (int r = 0; r < 4; r++) av[r] = sAtt[(ty + 16 * r) * 65 + j];
#pragma unroll
        for (int cc = 0; cc < 8; cc++) bv[cc] = sKV[j * 129 + tx + 16 * cc];
#pragma unroll
        for (int r = 0; r < 4; r++)
#pragma unroll
            for (int cc = 0; cc < 8; cc++) oA[r][cc] += av[r] * bv[cc];
    }

    const float* Sg = g_S + ((size_t)bh * NC + c) * 16384;
    for (int e0 = 0; e0 < 128; e0 += 16) {
        __syncthreads();
        for (int t0 = tid; t0 < 2048; t0 += 256) sS[t0] = Sg[(size_t)e0 * 128 + t0];
        __syncthreads();
#pragma unroll
        for (int e = 0; e < 16; e++) {
            float qv[4], sv[8];
#pragma unroll
            for (int r = 0; r < 4; r++) qv[r] = sQ[(ty + 16 * r) * 129 + e0 + e];
#pragma unroll
            for (int cc = 0; cc < 8; cc++) sv[cc] = sS[e * 128 + tx + 16 * cc];
#pragma unroll
            for (int r = 0; r < 4; r++)
#pragma unroll
                for (int cc = 0; cc < 8; cc++) oB[r][cc] += qv[r] * sv[cc];
        }
    }

    float* og = g_o + ((size_t)bh * TT + c * 64) * 128;
#pragma unroll
    for (int r = 0; r < 4; r++) {
        int i = ty + 16 * r;
        float qd = sEi[i + 1];  // q_dec[i] = e^{slope*(i+1)}
#pragma unroll
        for (int cc = 0; cc < 8; cc++)
            og[i * 128 + tx + 16 * cc] = oA[r][cc] + qd * oB[r][cc];
    }
}

// ---------------------------------------------------------------------------
// Group rmsnorm (per head, D=128) * g_norm_w * sigmoid-gate -> og [8192,2048]
// grid = (B*T, H), block = 128
// ---------------------------------------------------------------------------
__global__ __launch_bounds__(128) void norm_gate_k(const float* __restrict__ gnw) {
    const int bt = blockIdx.x, h = blockIdx.y, d = threadIdx.x;
    const int b = bt >> 12, t = bt & 4095;
    float x = g_o[((size_t)(b * NH + h) * TT + t) * 128 + d];
    float ss = x * x;
#pragma unroll
    for (int o = 16; o; o >>= 1) ss += __shfl_xor_sync(0xffffffffu, ss, o);
    __shared__ float red[4];
    if ((d & 31) == 0) red[d >> 5] = ss;
    __syncthreads();
    float tot = red[0] + red[1] + red[2] + red[3];
    float rs = rsqrtf(tot * (1.f / 128.f) + 1e-6f);
    const int ch = h * 128 + d;
    const float* gate = g_qkv + (size_t)8192 * 2048;
    float gv = gate[(size_t)bt * 2048 + ch];
    g_qkv[(size_t)bt * 2048 + ch] = gnw[ch] * (x * rs) * gv;
}

// ---------------------------------------------------------------------------
extern "C" void kernel_launch(void* const* d_in, const int* in_sizes, int n_in,
                              void* d_out, int out_size) {
    const float* hs   = (const float*)d_in[0];  // hidden_states [2,4096,2048]
    const float* wqkv = (const float*)d_in[1];  // [6144,2048]
    const float* qln  = (const float*)d_in[2];  // [128]
    const float* kln  = (const float*)d_in[3];  // [128]
    const float* gnw  = (const float*)d_in[4];  // [2048]
    const float* wg   = (const float*)d_in[5];  // [2048,2048]
    const float* wd   = (const float*)d_in[6];  // [2048,2048]
    const int*   pos  = (const int*)d_in[7];    // [2,4096]
    float* out = (float*)d_out;                 // [2,4096,2048]

    // resolve device-global addresses
    __nv_bfloat16 *gA = nullptr, *gB = nullptr;
    float *gQKV = nullptr, *gO = nullptr;
    cudaGetSymbolAddress((void**)&gA, g_A);
    cudaGetSymbolAddress((void**)&gB, g_B);
    cudaGetSymbolAddress((void**)&gQKV, g_qkv);
    cudaGetSymbolAddress((void**)&gO, g_o);

    // >48KB dynamic smem opt-in (idempotent)
    cudaFuncSetAttribute((const void*)chunk_kv_k,
                         cudaFuncAttributeMaxDynamicSharedMemorySize, 65792);
    cudaFuncSetAttribute((const void*)chunk_out_k,
                         cudaFuncAttributeMaxDynamicSharedMemorySize, 91140);
    cudaGetLastError();  // clear any benign error from in-capture attr set

    // bf16x3 operand preparation
    split_k<<<16384, 256>>>(hs,   gA, 8192 * 512, 0);                        // A' = hs
    split_k<<<12288, 256>>>(wqkv, gB, 6144 * 512, 1);                        // B' wqkv
    split_k<<<4096,  256>>>(wg,   gB + (size_t)6144 * 6144, 2048 * 512, 1);  // B' wg
    split_k<<<4096,  256>>>(wd,   gB + (size_t)8192 * 6144, 2048 * 512, 1);  // B' wd

    // qkv projection (tensor cores) + post-process
    mma_gemm<6144, 0><<<dim3(48, 64), 256>>>(gA, gB, gQKV);
    qkv_post_k<<<dim3(8192, 16), 128>>>(pos, qln, kln);

    // gate projection (overwrites upper half of g_qkv; qkv already consumed)
    mma_gemm<2048, 1><<<dim3(16, 64), 256>>>(gA, gB + (size_t)6144 * 6144,
                                             gQKV + (size_t)8192 * 2048);

    // chunked linear attention
    chunk_kv_k <<<dim3(NC, 32), 256, 65792>>>();
    scan_k     <<<dim3(32, 8), 256>>>();
    chunk_out_k<<<dim3(NC, 32), 256, 91140>>>();

    // group-norm * gate, then dense projection (tensor cores)
    norm_gate_k<<<dim3(8192, 16), 128>>>(gnw);
    split_k<<<16384, 256>>>(gQKV, gA, 8192 * 512, 0);                        // A' = og
    mma_gemm<2048, 0><<<dim3(16, 64), 256>>>(gA, gB + (size_t)8192 * 6144, out);
}

// round 7
// speedup vs baseline: 1.0760x; 1.0760x over previous
#include <cuda_runtime.h>
#include <cuda_bf16.h>
#include <cstdint>

// Problem constants (fixed by the reference)
#define TT 4096      // T
#define NH 16        // H
#define NC 64        // number of chunks (T / CHUNK)
// B=2, D=128, CHUNK=64, HID=2048, K3 = 3*2048 = 6144 (bf16x3 split-K)

// ---------------------------------------------------------------------------
// Scratch (device globals; no allocation allowed anywhere)
// ---------------------------------------------------------------------------
__device__ float g_qkv[50331648];            // 8192*6144 (later reused: og | gate)
__device__ float g_q[16777216];              // [B,H,T,D] = 32*4096*128
__device__ float g_k[16777216];
__device__ float g_v[16777216];
__device__ float g_U[33554432];              // [B,H,NC,128,128] decayed K^T V per chunk
__device__ float g_S[33554432];              // [B,H,NC,128,128] state entering each chunk
__device__ float g_o[16777216];              // [B,H,T,D] attention output
// bf16x3 operands: A' = [hi | lo | hi] (K'=6144), B' = [hi | hi | lo]
__device__ __nv_bfloat16 g_A[50331648];      // [8192, 6144]
__device__ __nv_bfloat16 g_B[62914560];      // [10240, 6144]: wqkv(6144) | wg(2048) | wd(2048)

__device__ __forceinline__ float head_slope(int h) {
    const float scale = 1.0f - 11.0f / 31.0f + 1e-5f;
    return -exp2f(-0.5f * (float)(h + 1)) * scale;
}

// ---------------------------------------------------------------------------
// bf16x3 split: in [rows,2048] fp32 -> out [rows,6144] bf16.
// bmode=0 (A side): segments {hi, lo, hi};  bmode=1 (B side): {hi, hi, lo}.
// ---------------------------------------------------------------------------
union Pack4 { __nv_bfloat16 b[4]; uint2 u; };

__global__ __launch_bounds__(256) void split_k(const float* __restrict__ in,
                                               __nv_bfloat16* __restrict__ out,
                                               int n4, int bmode) {
    int idx = blockIdx.x * 256 + threadIdx.x;
    if (idx >= n4) return;
    int r = idx >> 9, k4 = (idx & 511) << 2;
    float4 x = *(const float4*)(in + (size_t)r * 2048 + k4);
    float xs[4] = {x.x, x.y, x.z, x.w};
    Pack4 H, L;
#pragma unroll
    for (int j = 0; j < 4; j++) {
        __nv_bfloat16 h = __float2bfloat16(xs[j]);
        H.b[j] = h;
        L.b[j] = __float2bfloat16(xs[j] - __bfloat162float(h));
    }
    size_t base = (size_t)r * 6144 + k4;
    *(uint2*)(out + base) = H.u;
    if (bmode) {
        *(uint2*)(out + base + 2048) = H.u;
        *(uint2*)(out + base + 4096) = L.u;
    } else {
        *(uint2*)(out + base + 2048) = L.u;
        *(uint2*)(out + base + 4096) = H.u;
    }
}

// ---------------------------------------------------------------------------
// bf16 NT tensor-core GEMM: C[M,N] = A'[M,6144] * B'[N,6144]^T, fp32 accum.
// 128x128 CTA tile, 256 threads = 8 warps (2x4), warp tile 64x32,
// mma.sync.m16n8k16 with ldmatrix fragment loads. Double-buffered smem.
// ACT==1 -> sigmoid epilogue.
// ---------------------------------------------------------------------------
#define K3 6144

__device__ __forceinline__ void mma16816(float* c, const uint32_t* a, const uint32_t* b) {
    asm volatile(
        "mma.sync.aligned.m16n8k16.row.col.f32.bf16.bf16.f32 "
        "{%0,%1,%2,%3}, {%4,%5,%6,%7}, {%8,%9}, {%0,%1,%2,%3};"
        : "+f"(c[0]), "+f"(c[1]), "+f"(c[2]), "+f"(c[3])
        : "r"(a[0]), "r"(a[1]), "r"(a[2]), "r"(a[3]), "r"(b[0]), "r"(b[1]));
}

__device__ __forceinline__ void ldsm4(uint32_t* d, uint32_t addr) {
    asm volatile("ldmatrix.sync.aligned.m8n8.x4.shared.b16 {%0,%1,%2,%3}, [%4];"
                 : "=r"(d[0]), "=r"(d[1]), "=r"(d[2]), "=r"(d[3]) : "r"(addr));
}

template <int N, int ACT>
__global__ __launch_bounds__(256) void mma_gemm(const __nv_bfloat16* __restrict__ A,
                                                const __nv_bfloat16* __restrict__ B,
                                                float* __restrict__ C) {
    __shared__ __nv_bfloat16 As[2][128][40];   // 32-wide K slab + 8 pad (80B rows)
    __shared__ __nv_bfloat16 Bs[2][128][40];
    const int tid = threadIdx.x;
    const int m0 = blockIdx.y * 128, n0 = blockIdx.x * 128;
    const int lrow = tid >> 1, lseg = (tid & 1) * 16;
    const __nv_bfloat16* Ag = A + (size_t)(m0 + lrow) * K3 + lseg;
    const __nv_bfloat16* Bg = B + (size_t)(n0 + lrow) * K3 + lseg;

    const int wid = tid >> 5, lane = tid & 31;
    const int wm = wid >> 2, wn = wid & 3;
    const int grp = lane >> 2, qd = lane & 3;
    const int mbase = wm * 64, nbase = wn * 32;

    // ldmatrix per-lane offsets (elements). mi = lane>>3 (matrix index 0..3)
    const int mi = lane >> 3, r8 = lane & 7;
    // A tile mt (16x16): m0:(r,kk) m1:(r+8,kk) m2:(r,kk+8) m3:(r+8,kk+8)
    const int a_row_off = ((mi & 1) ? 8 : 0) + r8;
    const int a_k_off   = (mi >> 1) ? 8 : 0;
    // B tile pair p (16 cols x 16 k): m0:(c,kk) m1:(c,kk+8) m2:(c+8,kk) m3:(c+8,kk+8)
    const int b_col_off = ((mi >> 1) ? 8 : 0) + r8;
    const int b_k_off   = (mi & 1) ? 8 : 0;

    const uint32_t sAs = (uint32_t)__cvta_generic_to_shared(&As[0][0][0]);
    const uint32_t sBs = (uint32_t)__cvta_generic_to_shared(&Bs[0][0][0]);
    const uint32_t bufStride = 128 * 40 * 2;   // bytes per buffer

    float acc[4][4][4];
#pragma unroll
    for (int mt = 0; mt < 4; mt++)
#pragma unroll
        for (int nt = 0; nt < 4; nt++)
#pragma unroll
            for (int j = 0; j < 4; j++) acc[mt][nt][j] = 0.f;

    // preload slab 0
    {
        uint4 a0 = *(const uint4*)(Ag);
        uint4 a1 = *(const uint4*)(Ag + 8);
        uint4 b0 = *(const uint4*)(Bg);
        uint4 b1 = *(const uint4*)(Bg + 8);
        *(uint4*)&As[0][lrow][lseg]     = a0;
        *(uint4*)&As[0][lrow][lseg + 8] = a1;
        *(uint4*)&Bs[0][lrow][lseg]     = b0;
        *(uint4*)&Bs[0][lrow][lseg + 8] = b1;
    }
    __syncthreads();

    int buf = 0;
    for (int kt = 32; kt <= K3; kt += 32) {
        const bool more = (kt < K3);
        uint4 na0, na1, nb0, nb1;
        if (more) {
            na0 = *(const uint4*)(Ag + kt);
            na1 = *(const uint4*)(Ag + kt + 8);
            nb0 = *(const uint4*)(Bg + kt);
            nb1 = *(const uint4*)(Bg + kt + 8);
        }

        const uint32_t aB = sAs + buf * bufStride;
        const uint32_t bB = sBs + buf * bufStride;

#pragma unroll
        for (int kk = 0; kk < 32; kk += 16) {
            uint32_t au[4][4], bu[4][2];
#pragma unroll
            for (int mt = 0; mt < 4; mt++) {
                uint32_t addr = aB + ((mbase + mt * 16 + a_row_off) * 40 +
                                      kk + a_k_off) * 2;
                ldsm4(au[mt], addr);
            }
#pragma unroll
            for (int p = 0; p < 2; p++) {
                uint32_t d[4];
                uint32_t addr = bB + ((nbase + p * 16 + b_col_off) * 40 +
                                      kk + b_k_off) * 2;
                ldsm4(d, addr);
                bu[2 * p][0] = d[0]; bu[2 * p][1] = d[1];
                bu[2 * p + 1][0] = d[2]; bu[2 * p + 1][1] = d[3];
            }
#pragma unroll
            for (int mt = 0; mt < 4; mt++)
#pragma unroll
                for (int nt = 0; nt < 4; nt++)
                    mma16816(acc[mt][nt], au[mt], bu[nt]);
        }

        if (more) {
            buf ^= 1;
            *(uint4*)&As[buf][lrow][lseg]     = na0;
            *(uint4*)&As[buf][lrow][lseg + 8] = na1;
            *(uint4*)&Bs[buf][lrow][lseg]     = nb0;
            *(uint4*)&Bs[buf][lrow][lseg + 8] = nb1;
            __syncthreads();
        }
    }

    // epilogue
#pragma unroll
    for (int mt = 0; mt < 4; mt++) {
#pragma unroll
        for (int nt = 0; nt < 4; nt++) {
            int row = m0 + mbase + mt * 16 + grp;
            int col = n0 + nbase + nt * 8 + qd * 2;
            float v0 = acc[mt][nt][0], v1 = acc[mt][nt][1];
            float v2 = acc[mt][nt][2], v3 = acc[mt][nt][3];
            if (ACT == 1) {
                v0 = 1.f / (1.f + expf(-v0));
                v1 = 1.f / (1.f + expf(-v1));
                v2 = 1.f / (1.f + expf(-v2));
                v3 = 1.f / (1.f + expf(-v3));
            }
            *(float2*)&C[(size_t)row * N + col]       = make_float2(v0, v1);
            *(float2*)&C[(size_t)(row + 8) * N + col] = make_float2(v2, v3);
        }
    }
}

// ---------------------------------------------------------------------------
// QKV post-process: per-(b,t,h) rmsnorm on q,k (D=128), RoPE on first 64 dims,
// fold D^-0.5 into q, scatter q/k/v to [B,H,T,D].  grid = (B*T, H), block 128
// ---------------------------------------------------------------------------
__global__ __launch_bounds__(128) void qkv_post_k(const int* __restrict__ pos_ids,
                                                  const float* __restrict__ qw,
                                                  const float* __restrict__ kw) {
    const int bt = blockIdx.x, h = blockIdx.y, d = threadIdx.x;
    const int b = bt >> 12, t = bt & 4095;
    const float* base = g_qkv + (size_t)bt * 6144 + h * 128 + d;
    float qv = base[0];
    float kv = base[2048];
    float vv = base[4096];

    float sq = qv * qv, sk = kv * kv;
#pragma unroll
    for (int o = 16; o; o >>= 1) {
        sq += __shfl_xor_sync(0xffffffffu, sq, o);
        sk += __shfl_xor_sync(0xffffffffu, sk, o);
    }
    __shared__ float rq[4], rk[4];
    if ((d & 31) == 0) { rq[d >> 5] = sq; rk[d >> 5] = sk; }
    __syncthreads();
    float ssq = rq[0] + rq[1] + rq[2] + rq[3];
    float ssk = rk[0] + rk[1] + rk[2] + rk[3];
    float qn = qw[d] * (qv * rsqrtf(ssq * (1.f / 128.f) + 1e-6f));
    float kn = kw[d] * (kv * rsqrtf(ssk * (1.f / 128.f) + 1e-6f));

    __shared__ float bq[128], bk[128];
    bq[d] = qn; bk[d] = kn;
    __syncthreads();
    if (d < 64) {
        int i = d & 31;
        float inv = exp2f((float)(2 * i) * (-13.287712379549449f / 64.f));
        float ang = (float)pos_ids[bt] * inv;
        float cs, sn;
        sincosf(ang, &sn, &cs);
        if (d < 32) { qn = qn * cs - bq[d + 32] * sn; kn = kn * cs - bk[d + 32] * sn; }
        else        { qn = qn * cs + bq[d - 32] * sn; kn = kn * cs + bk[d - 32] * sn; }
    }
    const size_t oi = ((size_t)(b * NH + h) * TT + t) * 128 + d;
    g_q[oi] = qn * 0.08838834764831845f;  // D^-0.5 folded into q
    g_k[oi] = kn;
    g_v[oi] = vv;
}

// ---------------------------------------------------------------------------
// U_c[e,d] = sum_i exp(slope*(63-i)) * K[c,i,e] * V[c,i,d]   (128x128, K=64)
// grid = (NC, B*H), 256 threads, 8x8 per-thread tile. 64KB dynamic smem.
// ---------------------------------------------------------------------------
__global__ __launch_bounds__(256) void chunk_kv_k() {
    extern __shared__ float sm[];
    float* Ks = sm;               // 64*128
    float* Vs = sm + 8192;        // 64*128
    float* kd = sm + 16384;       // 64
    const int c = blockIdx.x, bh = blockIdx.y;
    const float slope = head_slope(bh & 15);
    const int tid = threadIdx.x, tx = tid & 15, ty = tid >> 4;
    const float* kg = g_k + ((size_t)bh * TT + c * 64) * 128;
    const float* vg = g_v + ((size_t)bh * TT + c * 64) * 128;
    for (int t0 = tid * 4; t0 < 8192; t0 += 1024) {
        *(float4*)(Ks + t0) = *(const float4*)(kg + t0);
        *(float4*)(Vs + t0) = *(const float4*)(vg + t0);
    }
    if (tid < 64) kd[tid] = expf(slope * (float)(63 - tid));
    __syncthreads();

    float acc[8][8];
#pragma unroll
    for (int r = 0; r < 8; r++)
#pragma unroll
        for (int cc = 0; cc < 8; cc++) acc[r][cc] = 0.f;

    for (int i = 0; i < 64; i++) {
        float w = kd[i];
        float4 a0 = *(const float4*)(Ks + i * 128 + ty * 8);
        float4 a1 = *(const float4*)(Ks + i * 128 + ty * 8 + 4);
        float4 b0 = *(const float4*)(Vs + i * 128 + tx * 8);
        float4 b1 = *(const float4*)(Vs + i * 128 + tx * 8 + 4);
        float ar[8] = {a0.x * w, a0.y * w, a0.z * w, a0.w * w,
                       a1.x * w, a1.y * w, a1.z * w, a1.w * w};
        float br[8] = {b0.x, b0.y, b0.z, b0.w, b1.x, b1.y, b1.z, b1.w};
#pragma unroll
        for (int r = 0; r < 8; r++)
#pragma unroll
            for (int cc = 0; cc < 8; cc++) acc[r][cc] += ar[r] * br[cc];
    }

    float* Ug = g_U + ((size_t)bh * NC + c) * 16384;
#pragma unroll
    for (int r = 0; r < 8; r++) {
        float* p = Ug + (ty * 8 + r) * 128 + tx * 8;
        *(float4*)p       = make_float4(acc[r][0], acc[r][1], acc[r][2], acc[r][3]);
        *(float4*)(p + 4) = make_float4(acc[r][4], acc[r][5], acc[r][6], acc[r][7]);
    }
}

// ---------------------------------------------------------------------------
// Prefix scan over chunks: S[0]=0; S[c] = lam*S[c-1] + U[c-1], lam = e^{slope*64}
// ---------------------------------------------------------------------------
__global__ __launch_bounds__(256) void scan_k() {
    const int bh = blockIdx.x, part = blockIdx.y;
    const float lam = expf(head_slope(bh & 15) * 64.f);
    const int e0 = part * 2048 + threadIdx.x;
    float s[8];
#pragma unroll
    for (int j = 0; j < 8; j++) s[j] = 0.f;
    float* Sb = g_S + (size_t)bh * NC * 16384;
    const float* Ub = g_U + (size_t)bh * NC * 16384;
#pragma unroll
    for (int j = 0; j < 8; j++) Sb[e0 + j * 256] = 0.f;
    for (int c = 1; c < NC; c++) {
        const float* u = Ub + (size_t)(c - 1) * 16384;
        float* so = Sb + (size_t)c * 16384;
#pragma unroll
        for (int j = 0; j < 8; j++) {
            s[j] = lam * s[j] + u[e0 + j * 256];
            so[e0 + j * 256] = s[j];
        }
    }
}

// ---------------------------------------------------------------------------
// Chunk output: o = mask(Q K^T) V + qdec * (Q @ S_c)     (64x128 per block)
// grid = (NC, B*H), 256 threads (16x16), ~89KB dynamic smem.
// ---------------------------------------------------------------------------
__global__ __launch_bounds__(256) void chunk_out_k() {
    extern __shared__ float sm[];
    float* sQ   = sm;                    // 64*129
    float* sKV  = sm + 64 * 129;         // 64*129 (K, then V)
    float* sAtt = sm + 2 * 64 * 129;     // 64*65
    float* sS   = sAtt + 64 * 65;        // 16*128
    float* sEi  = sS + 16 * 128;         // 65 : e^{slope*t}, t=0..64
    const int c = blockIdx.x, bh = blockIdx.y;
    const float slope = head_slope(bh & 15);
    const int tid = threadIdx.x, tx = tid & 15, ty = tid >> 4;
    const float* qg = g_q + ((size_t)bh * TT + c * 64) * 128;
    const float* kg = g_k + ((size_t)bh * TT + c * 64) * 128;
    const float* vg = g_v + ((size_t)bh * TT + c * 64) * 128;

    for (int t0 = tid; t0 < 8192; t0 += 256) {
        int r = t0 >> 7, cc = t0 & 127;
        sQ[r * 129 + cc]  = qg[t0];
        sKV[r * 129 + cc] = kg[t0];
    }
    if (tid < 65) sEi[tid] = expf(slope * (float)tid);
    __syncthreads();

    float att[4][4];
#pragma unroll
    for (int r = 0; r < 4; r++)
#pragma unroll
        for (int cc = 0; cc < 4; cc++) att[r][cc] = 0.f;
    for (int d = 0; d < 128; d++) {
        float qv[4], kv[4];
#pragma unroll
        for (int r = 0; r < 4; r++) qv[r] = sQ[(ty + 16 * r) * 129 + d];
#pragma unroll
        for (int cc = 0; cc < 4; cc++) kv[cc] = sKV[(tx + 16 * cc) * 129 + d];
#pragma unroll
        for (int r = 0; r < 4; r++)
#pragma unroll
            for (int cc = 0; cc < 4; cc++) att[r][cc] += qv[r] * kv[cc];
    }
#pragma unroll
    for (int r = 0; r < 4; r++) {
        int i = ty + 16 * r;
#pragma unroll
        for (int cc = 0; cc < 4; cc++) {
            int j = tx + 16 * cc;
            sAtt[i * 65 + j] = (i >= j) ? att[r][cc] * sEi[i - j] : 0.f;
        }
    }
    __syncthreads();

    for (int t0 = tid; t0 < 8192; t0 += 256) {
        int r = t0 >> 7, cc = t0 & 127;
        sKV[r * 129 + cc] = vg[t0];
    }
    __syncthreads();

    float oA[4][8], oB[4][8];
#pragma unroll
    for (int r = 0; r < 4; r++)
#pragma unroll
        for (int cc = 0; cc < 8; cc++) { oA[r][cc] = 0.f; oB[r][cc] = 0.f; }

    for (int j = 0; j < 64; j++) {
        float av[4], bv[8];
#pragma unroll
        for (int r = 0; r < 4; r++) av[r] = sAtt[(ty + 16 * r) * 65 + j];
#pragma unroll
        for (int cc = 0; cc < 8; cc++) bv[cc] = sKV[j * 129 + tx + 16 * cc];
#pragma unroll
        for (int r = 0; r < 4; r++)
#pragma unroll
            for (int cc = 0; cc < 8; cc++) oA[r][cc] += av[r] * bv[cc];
    }

    const float* Sg = g_S + ((size_t)bh * NC + c) * 16384;
    for (int e0 = 0; e0 < 128; e0 += 16) {
        __syncthreads();
        for (int t0 = tid; t0 < 2048; t0 += 256) sS[t0] = Sg[(size_t)e0 * 128 + t0];
        __syncthreads();
#pragma unroll
        for (int e = 0; e < 16; e++) {
            float qv[4], sv[8];
#pragma unroll
            for (int r = 0; r < 4; r++) qv[r] = sQ[(ty + 16 * r) * 129 + e0 + e];
#pragma unroll
            for (int cc = 0; cc < 8; cc++) sv[cc] = sS[e * 128 + tx + 16 * cc];
#pragma unroll
            for (int r = 0; r < 4; r++)
#pragma unroll
                for (int cc = 0; cc < 8; cc++) oB[r][cc] += qv[r] * sv[cc];
        }
    }

    float* og = g_o + ((size_t)bh * TT + c * 64) * 128;
#pragma unroll
    for (int r = 0; r < 4; r++) {
        int i = ty + 16 * r;
        float qd = sEi[i + 1];  // q_dec[i] = e^{slope*(i+1)}
#pragma unroll
        for (int cc = 0; cc < 8; cc++)
            og[i * 128 + tx + 16 * cc] = oA[r][cc] + qd * oB[r][cc];
    }
}

// ---------------------------------------------------------------------------
// Group rmsnorm (per head, D=128) * g_norm_w * sigmoid-gate -> og [8192,2048]
// ---------------------------------------------------------------------------
__global__ __launch_bounds__(128) void norm_gate_k(const float* __restrict__ gnw) {
    const int bt = blockIdx.x, h = blockIdx.y, d = threadIdx.x;
    const int b = bt >> 12, t = bt & 4095;
    float x = g_o[((size_t)(b * NH + h) * TT + t) * 128 + d];
    float ss = x * x;
#pragma unroll
    for (int o = 16; o; o >>= 1) ss += __shfl_xor_sync(0xffffffffu, ss, o);
    __shared__ float red[4];
    if ((d & 31) == 0) red[d >> 5] = ss;
    __syncthreads();
    float tot = red[0] + red[1] + red[2] + red[3];
    float rs = rsqrtf(tot * (1.f / 128.f) + 1e-6f);
    const int ch = h * 128 + d;
    const float* gate = g_qkv + (size_t)8192 * 2048;
    float gv = gate[(size_t)bt * 2048 + ch];
    g_qkv[(size_t)bt * 2048 + ch] = gnw[ch] * (x * rs) * gv;
}

// ---------------------------------------------------------------------------
extern "C" void kernel_launch(void* const* d_in, const int* in_sizes, int n_in,
                              void* d_out, int out_size) {
    const float* hs   = (const float*)d_in[0];  // hidden_states [2,4096,2048]
    const float* wqkv = (const float*)d_in[1];  // [6144,2048]
    const float* qln  = (const float*)d_in[2];  // [128]
    const float* kln  = (const float*)d_in[3];  // [128]
    const float* gnw  = (const float*)d_in[4];  // [2048]
    const float* wg   = (const float*)d_in[5];  // [2048,2048]
    const float* wd   = (const float*)d_in[6];  // [2048,2048]
    const int*   pos  = (const int*)d_in[7];    // [2,4096]
    float* out = (float*)d_out;                 // [2,4096,2048]

    __nv_bfloat16 *gA = nullptr, *gB = nullptr;
    float *gQKV = nullptr;
    cudaGetSymbolAddress((void**)&gA, g_A);
    cudaGetSymbolAddress((void**)&gB, g_B);
    cudaGetSymbolAddress((void**)&gQKV, g_qkv);

    cudaFuncSetAttribute((const void*)chunk_kv_k,
                         cudaFuncAttributeMaxDynamicSharedMemorySize, 65792);
    cudaFuncSetAttribute((const void*)chunk_out_k,
                         cudaFuncAttributeMaxDynamicSharedMemorySize, 91140);
    cudaGetLastError();  // clear any benign error from in-capture attr set

    // bf16x3 operand preparation
    split_k<<<16384, 256>>>(hs,   gA, 8192 * 512, 0);                        // A' = hs
    split_k<<<12288, 256>>>(wqkv, gB, 6144 * 512, 1);                        // B' wqkv
    split_k<<<4096,  256>>>(wg,   gB + (size_t)6144 * 6144, 2048 * 512, 1);  // B' wg
    split_k<<<4096,  256>>>(wd,   gB + (size_t)8192 * 6144, 2048 * 512, 1);  // B' wd

    // qkv projection (tensor cores) + post-process
    mma_gemm<6144, 0><<<dim3(48, 64), 256>>>(gA, gB, gQKV);
    qkv_post_k<<<dim3(8192, 16), 128>>>(pos, qln, kln);

    // gate projection
    mma_gemm<2048, 1><<<dim3(16, 64), 256>>>(gA, gB + (size_t)6144 * 6144,
                                             gQKV + (size_t)8192 * 2048);

    // chunked linear attention
    chunk_kv_k <<<dim3(NC, 32), 256, 65792>>>();
    scan_k     <<<dim3(32, 8), 256>>>();
    chunk_out_k<<<dim3(NC, 32), 256, 91140>>>();

    // group-norm * gate, then dense projection (tensor cores)
    norm_gate_k<<<dim3(8192, 16), 128>>>(gnw);
    split_k<<<16384, 256>>>(gQKV, gA, 8192 * 512, 0);                        // A' = og
    mma_gemm<2048, 0><<<dim3(16, 64), 256>>>(gA, gB + (size_t)8192 * 6144, out);
}

// round 13
// speedup vs baseline: 1.2650x; 1.1757x over previous
#include <cuda_runtime.h>
#include <cuda_bf16.h>
#include <cstdint>

// Problem constants (fixed by the reference)
#define TT 4096      // T
#define NH 16        // H
#define NC 64        // number of chunks (T / CHUNK)
// B=2, D=128, CHUNK=64, HID=2048, K3 = 3*2048 = 6144 (bf16x3 split-K)

// ---------------------------------------------------------------------------
// Scratch (device globals; no allocation allowed anywhere)
// ---------------------------------------------------------------------------
__device__ float g_qkv[50331648];            // 8192*6144 (later reused: og | gate)
__device__ float g_q[16777216];              // [B,H,T,D] = 32*4096*128
__device__ float g_k[16777216];
__device__ float g_v[16777216];
__device__ float g_U[33554432];              // [B,H,NC,128,128] decayed K^T V per chunk
__device__ float g_S[33554432];              // [B,H,NC,128,128] state entering each chunk
__device__ float g_o[16777216];              // [B,H,T,D] attention output
// bf16x3 operands: A' = [hi | lo | hi] (K'=6144), B' = [hi | hi | lo]
__device__ __nv_bfloat16 g_A[50331648];      // [8192, 6144]
__device__ __nv_bfloat16 g_B[62914560];      // [10240, 6144]: wqkv(6144) | wg(2048) | wd(2048)

__device__ __forceinline__ float head_slope(int h) {
    const float scale = 1.0f - 11.0f / 31.0f + 1e-5f;
    return -exp2f(-0.5f * (float)(h + 1)) * scale;
}

// ---------------------------------------------------------------------------
// bf16x3 split: in [rows,2048] fp32 -> out [rows,6144] bf16.
// bmode=0 (A side): segments {hi, lo, hi};  bmode=1 (B side): {hi, hi, lo}.
// ---------------------------------------------------------------------------
union Pack4 { __nv_bfloat16 b[4]; uint2 u; };

__global__ __launch_bounds__(256) void split_k(const float* __restrict__ in,
                                               __nv_bfloat16* __restrict__ out,
                                               int n4, int bmode) {
    int idx = blockIdx.x * 256 + threadIdx.x;
    if (idx >= n4) return;
    int r = idx >> 9, k4 = (idx & 511) << 2;
    float4 x = *(const float4*)(in + (size_t)r * 2048 + k4);
    float xs[4] = {x.x, x.y, x.z, x.w};
    Pack4 H, L;
#pragma unroll
    for (int j = 0; j < 4; j++) {
        __nv_bfloat16 h = __float2bfloat16(xs[j]);
        H.b[j] = h;
        L.b[j] = __float2bfloat16(xs[j] - __bfloat162float(h));
    }
    size_t base = (size_t)r * 6144 + k4;
    *(uint2*)(out + base) = H.u;
    if (bmode) {
        *(uint2*)(out + base + 2048) = H.u;
        *(uint2*)(out + base + 4096) = L.u;
    } else {
        *(uint2*)(out + base + 2048) = L.u;
        *(uint2*)(out + base + 4096) = H.u;
    }
}

// ---------------------------------------------------------------------------
// bf16 NT tensor-core GEMM: C[M,N] = A'[M,6144] * B'[N,6144]^T, fp32 accum.
// 128x128 CTA tile, 256 threads = 8 warps (2x4), warp tile 64x32,
// mma.sync.m16n8k16 + ldmatrix. 3-stage cp.async pipeline (prefetch dist 2).
// ACT==1 -> sigmoid epilogue.
// ---------------------------------------------------------------------------
#define K3 6144
#define STAGES 3
// per-stage: A tile 128 rows x 40 elems (80B rows) = 10240 B, same for B
#define STAGE_BYTES 20480
#define GEMM_SMEM (STAGES * STAGE_BYTES)   // 61440

__device__ __forceinline__ void mma16816(float* c, const uint32_t* a, const uint32_t* b) {
    asm volatile(
        "mma.sync.aligned.m16n8k16.row.col.f32.bf16.bf16.f32 "
        "{%0,%1,%2,%3}, {%4,%5,%6,%7}, {%8,%9}, {%0,%1,%2,%3};"
        : "+f"(c[0]), "+f"(c[1]), "+f"(c[2]), "+f"(c[3])
        : "r"(a[0]), "r"(a[1]), "r"(a[2]), "r"(a[3]), "r"(b[0]), "r"(b[1]));
}

__device__ __forceinline__ void ldsm4(uint32_t* d, uint32_t addr) {
    asm volatile("ldmatrix.sync.aligned.m8n8.x4.shared.b16 {%0,%1,%2,%3}, [%4];"
                 : "=r"(d[0]), "=r"(d[1]), "=r"(d[2]), "=r"(d[3]) : "r"(addr));
}

__device__ __forceinline__ void cpa16(uint32_t dst, const void* src) {
    asm volatile("cp.async.ca.shared.global [%0], [%1], 16;"
                 :: "r"(dst), "l"(src));
}

template <int N, int ACT>
__global__ __launch_bounds__(256) void mma_gemm(const __nv_bfloat16* __restrict__ A,
                                                const __nv_bfloat16* __restrict__ B,
                                                float* __restrict__ C) {
    extern __shared__ char smem[];
    const uint32_t sBase = (uint32_t)__cvta_generic_to_shared(smem);

    const int tid = threadIdx.x;
    const int m0 = blockIdx.y * 128, n0 = blockIdx.x * 128;
    const int lrow = tid >> 1, lseg = (tid & 1) * 16;
    const __nv_bfloat16* Ag = A + (size_t)(m0 + lrow) * K3 + lseg;
    const __nv_bfloat16* Bg = B + (size_t)(n0 + lrow) * K3 + lseg;
    const uint32_t dstOff = (uint32_t)(lrow * 80 + lseg * 2);  // within a tile

    const int wid = tid >> 5, lane = tid & 31;
    const int wm = wid >> 2, wn = wid & 3;
    const int grp = lane >> 2, qd = lane & 3;
    const int mbase = wm * 64, nbase = wn * 32;

    // ldmatrix per-lane offsets (elements). mi = lane>>3 (matrix index 0..3)
    const int mi = lane >> 3, r8 = lane & 7;
    const int a_row_off = ((mi & 1) ? 8 : 0) + r8;
    const int a_k_off   = (mi >> 1) ? 8 : 0;
    const int b_col_off = ((mi >> 1) ? 8 : 0) + r8;
    const int b_k_off   = (mi & 1) ? 8 : 0;

    float acc[4][4][4];
#pragma unroll
    for (int mt = 0; mt < 4; mt++)
#pragma unroll
        for (int nt = 0; nt < 4; nt++)
#pragma unroll
            for (int j = 0; j < 4; j++) acc[mt][nt][j] = 0.f;

    const int NT = K3 / 32;   // 192 K-slabs

    // issue one stage's cp.async (4x16B per thread: 2 for A, 2 for B)
    auto issue = [&](int tile, int st) {
        uint32_t base = sBase + st * STAGE_BYTES;
        int kt = tile * 32;
        cpa16(base + dstOff,                 Ag + kt);
        cpa16(base + dstOff + 16,            Ag + kt + 8);
        cpa16(base + 10240 + dstOff,         Bg + kt);
        cpa16(base + 10240 + dstOff + 16,    Bg + kt + 8);
    };

    // prologue: stages 0,1 in flight
    issue(0, 0);
    asm volatile("cp.async.commit_group;");
    issue(1, 1);
    asm volatile("cp.async.commit_group;");

    int st = 0;
    for (int it = 0; it < NT; it++) {
        asm volatile("cp.async.wait_group 1;");
        __syncthreads();

        const uint32_t aB = sBase + st * STAGE_BYTES;
        const uint32_t bB = aB + 10240;

#pragma unroll
        for (int kk = 0; kk < 32; kk += 16) {
            uint32_t au[4][4], bu[4][2];
#pragma unroll
            for (int mt = 0; mt < 4; mt++) {
                uint32_t addr = aB + ((mbase + mt * 16 + a_row_off) * 40 +
                                      kk + a_k_off) * 2;
                ldsm4(au[mt], addr);
            }
#pragma unroll
            for (int p = 0; p < 2; p++) {
                uint32_t d[4];
                uint32_t addr = bB + ((nbase + p * 16 + b_col_off) * 40 +
                                      kk + b_k_off) * 2;
                ldsm4(d, addr);
                bu[2 * p][0] = d[0]; bu[2 * p][1] = d[1];
                bu[2 * p + 1][0] = d[2]; bu[2 * p + 1][1] = d[3];
            }
#pragma unroll
            for (int mt = 0; mt < 4; mt++)
#pragma unroll
                for (int nt = 0; nt < 4; nt++)
                    mma16816(acc[mt][nt], au[mt], bu[nt]);
        }

        // refill the buffer freed at the last barrier (st+2 mod 3 == st-1 mod 3)
        if (it + 2 < NT) {
            int nst = st + 2; if (nst >= STAGES) nst -= STAGES;
            issue(it + 2, nst);
        }
        asm volatile("cp.async.commit_group;");

        if (++st == STAGES) st = 0;
    }

    // epilogue
#pragma unroll
    for (int mt = 0; mt < 4; mt++) {
#pragma unroll
        for (int nt = 0; nt < 4; nt++) {
            int row = m0 + mbase + mt * 16 + grp;
            int col = n0 + nbase + nt * 8 + qd * 2;
            float v0 = acc[mt][nt][0], v1 = acc[mt][nt][1];
            float v2 = acc[mt][nt][2], v3 = acc[mt][nt][3];
            if (ACT == 1) {
                v0 = 1.f / (1.f + expf(-v0));
                v1 = 1.f / (1.f + expf(-v1));
                v2 = 1.f / (1.f + expf(-v2));
                v3 = 1.f / (1.f + expf(-v3));
            }
            *(float2*)&C[(size_t)row * N + col]       = make_float2(v0, v1);
            *(float2*)&C[(size_t)(row + 8) * N + col] = make_float2(v2, v3);
        }
    }
}

// ---------------------------------------------------------------------------
// QKV post-process: per-(b,t,h) rmsnorm on q,k (D=128), RoPE on first 64 dims,
// fold D^-0.5 into q, scatter q/k/v to [B,H,T,D].  grid = (B*T, H), block 128
// ---------------------------------------------------------------------------
__global__ __launch_bounds__(128) void qkv_post_k(const int* __restrict__ pos_ids,
                                                  const float* __restrict__ qw,
                                                  const float* __restrict__ kw) {
    const int bt = blockIdx.x, h = blockIdx.y, d = threadIdx.x;
    const int b = bt >> 12, t = bt & 4095;
    const float* base = g_qkv + (size_t)bt * 6144 + h * 128 + d;
    float qv = base[0];
    float kv = base[2048];
    float vv = base[4096];

    float sq = qv * qv, sk = kv * kv;
#pragma unroll
    for (int o = 16; o; o >>= 1) {
        sq += __shfl_xor_sync(0xffffffffu, sq, o);
        sk += __shfl_xor_sync(0xffffffffu, sk, o);
    }
    __shared__ float rq[4], rk[4];
    if ((d & 31) == 0) { rq[d >> 5] = sq; rk[d >> 5] = sk; }
    __syncthreads();
    float ssq = rq[0] + rq[1] + rq[2] + rq[3];
    float ssk = rk[0] + rk[1] + rk[2] + rk[3];
    float qn = qw[d] * (qv * rsqrtf(ssq * (1.f / 128.f) + 1e-6f));
    float kn = kw[d] * (kv * rsqrtf(ssk * (1.f / 128.f) + 1e-6f));

    __shared__ float bq[128], bk[128];
    bq[d] = qn; bk[d] = kn;
    __syncthreads();
    if (d < 64) {
        int i = d & 31;
        float inv = exp2f((float)(2 * i) * (-13.287712379549449f / 64.f));
        float ang = (float)pos_ids[bt] * inv;
        float cs, sn;
        sincosf(ang, &sn, &cs);
        if (d < 32) { qn = qn * cs - bq[d + 32] * sn; kn = kn * cs - bk[d + 32] * sn; }
        else        { qn = qn * cs + bq[d - 32] * sn; kn = kn * cs + bk[d - 32] * sn; }
    }
    const size_t oi = ((size_t)(b * NH + h) * TT + t) * 128 + d;
    g_q[oi] = qn * 0.08838834764831845f;  // D^-0.5 folded into q
    g_k[oi] = kn;
    g_v[oi] = vv;
}

// ---------------------------------------------------------------------------
// U_c[e,d] = sum_i exp(slope*(63-i)) * K[c,i,e] * V[c,i,d]   (128x128, K=64)
// grid = (NC, B*H), 256 threads, 8x8 per-thread tile. 64KB dynamic smem.
// ---------------------------------------------------------------------------
__global__ __launch_bounds__(256) void chunk_kv_k() {
    extern __shared__ float sm[];
    float* Ks = sm;               // 64*128
    float* Vs = sm + 8192;        // 64*128
    float* kd = sm + 16384;       // 64
    const int c = blockIdx.x, bh = blockIdx.y;
    const float slope = head_slope(bh & 15);
    const int tid = threadIdx.x, tx = tid & 15, ty = tid >> 4;
    const float* kg = g_k + ((size_t)bh * TT + c * 64) * 128;
    const float* vg = g_v + ((size_t)bh * TT + c * 64) * 128;
    for (int t0 = tid * 4; t0 < 8192; t0 += 1024) {
        *(float4*)(Ks + t0) = *(const float4*)(kg + t0);
        *(float4*)(Vs + t0) = *(const float4*)(vg + t0);
    }
    if (tid < 64) kd[tid] = expf(slope * (float)(63 - tid));
    __syncthreads();

    float acc[8][8];
#pragma unroll
    for (int r = 0; r < 8; r++)
#pragma unroll
        for (int cc = 0; cc < 8; cc++) acc[r][cc] = 0.f;

    for (int i = 0; i < 64; i++) {
        float w = kd[i];
        float4 a0 = *(const float4*)(Ks + i * 128 + ty * 8);
        float4 a1 = *(const float4*)(Ks + i * 128 + ty * 8 + 4);
        float4 b0 = *(const float4*)(Vs + i * 128 + tx * 8);
        float4 b1 = *(const float4*)(Vs + i * 128 + tx * 8 + 4);
        float ar[8] = {a0.x * w, a0.y * w, a0.z * w, a0.w * w,
                       a1.x * w, a1.y * w, a1.z * w, a1.w * w};
        float br[8] = {b0.x, b0.y, b0.z, b0.w, b1.x, b1.y, b1.z, b1.w};
#pragma unroll
        for (int r = 0; r < 8; r++)
#pragma unroll
            for (int cc = 0; cc < 8; cc++) acc[r][cc] += ar[r] * br[cc];
    }

    float* Ug = g_U + ((size_t)bh * NC + c) * 16384;
#pragma unroll
    for (int r = 0; r < 8; r++) {
        float* p = Ug + (ty * 8 + r) * 128 + tx * 8;
        *(float4*)p       = make_float4(acc[r][0], acc[r][1], acc[r][2], acc[r][3]);
        *(float4*)(p + 4) = make_float4(acc[r][4], acc[r][5], acc[r][6], acc[r][7]);
    }
}

// ---------------------------------------------------------------------------
// Prefix scan over chunks: S[0]=0; S[c] = lam*S[c-1] + U[c-1], lam = e^{slope*64}
// ---------------------------------------------------------------------------
__global__ __launch_bounds__(256) void scan_k() {
    const int bh = blockIdx.x, part = blockIdx.y;
    const float lam = expf(head_slope(bh & 15) * 64.f);
    const int e0 = part * 2048 + threadIdx.x;
    float s[8];
#pragma unroll
    for (int j = 0; j < 8; j++) s[j] = 0.f;
    float* Sb = g_S + (size_t)bh * NC * 16384;
    const float* Ub = g_U + (size_t)bh * NC * 16384;
#pragma unroll
    for (int j = 0; j < 8; j++) Sb[e0 + j * 256] = 0.f;
    for (int c = 1; c < NC; c++) {
        const float* u = Ub + (size_t)(c - 1) * 16384;
        float* so = Sb + (size_t)c * 16384;
#pragma unroll
        for (int j = 0; j < 8; j++) {
            s[j] = lam * s[j] + u[e0 + j * 256];
            so[e0 + j * 256] = s[j];
        }
    }
}

// ---------------------------------------------------------------------------
// Chunk output: o = mask(Q K^T) V + qdec * (Q @ S_c)     (64x128 per block)
// grid = (NC, B*H), 256 threads (16x16), ~89KB dynamic smem.
// ---------------------------------------------------------------------------
__global__ __launch_bounds__(256) void chunk_out_k() {
    extern __shared__ float sm[];
    float* sQ   = sm;                    // 64*129
    float* sKV  = sm + 64 * 129;         // 64*129 (K, then V)
    float* sAtt = sm + 2 * 64 * 129;     // 64*65
    float* sS   = sAtt + 64 * 65;        // 16*128
    float* sEi  = sS + 16 * 128;         // 65 : e^{slope*t}, t=0..64
    const int c = blockIdx.x, bh = blockIdx.y;
    const float slope = head_slope(bh & 15);
    const int tid = threadIdx.x, tx = tid & 15, ty = tid >> 4;
    const float* qg = g_q + ((size_t)bh * TT + c * 64) * 128;
    const float* kg = g_k + ((size_t)bh * TT + c * 64) * 128;
    const float* vg = g_v + ((size_t)bh * TT + c * 64) * 128;

    for (int t0 = tid; t0 < 8192; t0 += 256) {
        int r = t0 >> 7, cc = t0 & 127;
        sQ[r * 129 + cc]  = qg[t0];
        sKV[r * 129 + cc] = kg[t0];
    }
    if (tid < 65) sEi[tid] = expf(slope * (float)tid);
    __syncthreads();

    float att[4][4];
#pragma unroll
    for (int r = 0; r < 4; r++)
#pragma unroll
        for (int cc = 0; cc < 4; cc++) att[r][cc] = 0.f;
    for (int d = 0; d < 128; d++) {
        float qv[4], kv[4];
#pragma unroll
        for (int r = 0; r < 4; r++) qv[r] = sQ[(ty + 16 * r) * 129 + d];
#pragma unroll
        for (int cc = 0; cc < 4; cc++) kv[cc] = sKV[(tx + 16 * cc) * 129 + d];
#pragma unroll
        for (int r = 0; r < 4; r++)
#pragma unroll
            for (int cc = 0; cc < 4; cc++) att[r][cc] += qv[r] * kv[cc];
    }
#pragma unroll
    for (int r = 0; r < 4; r++) {
        int i = ty + 16 * r;
#pragma unroll
        for (int cc = 0; cc < 4; cc++) {
            int j = tx + 16 * cc;
            sAtt[i * 65 + j] = (i >= j) ? att[r][cc] * sEi[i - j] : 0.f;
        }
    }
    __syncthreads();

    for (int t0 = tid; t0 < 8192; t0 += 256) {
        int r = t0 >> 7, cc = t0 & 127;
        sKV[r * 129 + cc] = vg[t0];
    }
    __syncthreads();

    float oA[4][8], oB[4][8];
#pragma unroll
    for (int r = 0; r < 4; r++)
#pragma unroll
        for (int cc = 0; cc < 8; cc++) { oA[r][cc] = 0.f; oB[r][cc] = 0.f; }

    for (int j = 0; j < 64; j++) {
        float av[4], bv[8];
#pragma unroll
        for (int r = 0; r < 4; r++) av[r] = sAtt[(ty + 16 * r) * 65 + j];
#pragma unroll
        for (int cc = 0; cc < 8; cc++) bv[cc] = sKV[j * 129 + tx + 16 * cc];
#pragma unroll
        for (int r = 0; r < 4; r++)
#pragma unroll
            for (int cc = 0; cc < 8; cc++) oA[r][cc] += av[r] * bv[cc];
    }

    const float* Sg = g_S + ((size_t)bh * NC + c) * 16384;
    for (int e0 = 0; e0 < 128; e0 += 16) {
        __syncthreads();
        for (int t0 = tid; t0 < 2048; t0 += 256) sS[t0] = Sg[(size_t)e0 * 128 + t0];
        __syncthreads();
#pragma unroll
        for (int e = 0; e < 16; e++) {
            float qv[4], sv[8];
#pragma unroll
            for (int r = 0; r < 4; r++) qv[r] = sQ[(ty + 16 * r) * 129 + e0 + e];
#pragma unroll
            for (int cc = 0; cc < 8; cc++) sv[cc] = sS[e * 128 + tx + 16 * cc];
#pragma unroll
            for (int r = 0; r < 4; r++)
#pragma unroll
                for (int cc = 0; cc < 8; cc++) oB[r][cc] += qv[r] * sv[cc];
        }
    }

    float* og = g_o + ((size_t)bh * TT + c * 64) * 128;
#pragma unroll
    for (int r = 0; r < 4; r++) {
        int i = ty + 16 * r;
        float qd = sEi[i + 1];  // q_dec[i] = e^{slope*(i+1)}
#pragma unroll
        for (int cc = 0; cc < 8; cc++)
            og[i * 128 + tx + 16 * cc] = oA[r][cc] + qd * oB[r][cc];
    }
}

// ---------------------------------------------------------------------------
// Group rmsnorm (per head, D=128) * g_norm_w * sigmoid-gate -> og [8192,2048]
// ---------------------------------------------------------------------------
__global__ __launch_bounds__(128) void norm_gate_k(const float* __restrict__ gnw) {
    const int bt = blockIdx.x, h = blockIdx.y, d = threadIdx.x;
    const int b = bt >> 12, t = bt & 4095;
    float x = g_o[((size_t)(b * NH + h) * TT + t) * 128 + d];
    float ss = x * x;
#pragma unroll
    for (int o = 16; o; o >>= 1) ss += __shfl_xor_sync(0xffffffffu, ss, o);
    __shared__ float red[4];
    if ((d & 31) == 0) red[d >> 5] = ss;
    __syncthreads();
    float tot = red[0] + red[1] + red[2] + red[3];
    float rs = rsqrtf(tot * (1.f / 128.f) + 1e-6f);
    const int ch = h * 128 + d;
    const float* gate = g_qkv + (size_t)8192 * 2048;
    float gv = gate[(size_t)bt * 2048 + ch];
    g_qkv[(size_t)bt * 2048 + ch] = gnw[ch] * (x * rs) * gv;
}

// ---------------------------------------------------------------------------
extern "C" void kernel_launch(void* const* d_in, const int* in_sizes, int n_in,
                              void* d_out, int out_size) {
    const float* hs   = (const float*)d_in[0];  // hidden_states [2,4096,2048]
    const float* wqkv = (const float*)d_in[1];  // [6144,2048]
    const float* qln  = (const float*)d_in[2];  // [128]
    const float* kln  = (const float*)d_in[3];  // [128]
    const float* gnw  = (const float*)d_in[4];  // [2048]
    const float* wg   = (const float*)d_in[5];  // [2048,2048]
    const float* wd   = (const float*)d_in[6];  // [2048,2048]
    const int*   pos  = (const int*)d_in[7];    // [2,4096]
    float* out = (float*)d_out;                 // [2,4096,2048]

    __nv_bfloat16 *gA = nullptr, *gB = nullptr;
    float *gQKV = nullptr;
    cudaGetSymbolAddress((void**)&gA, g_A);
    cudaGetSymbolAddress((void**)&gB, g_B);
    cudaGetSymbolAddress((void**)&gQKV, g_qkv);

    cudaFuncSetAttribute((const void*)chunk_kv_k,
                         cudaFuncAttributeMaxDynamicSharedMemorySize, 65792);
    cudaFuncSetAttribute((const void*)chunk_out_k,
                         cudaFuncAttributeMaxDynamicSharedMemorySize, 91140);
    cudaFuncSetAttribute((const void*)mma_gemm<6144, 0>,
                         cudaFuncAttributeMaxDynamicSharedMemorySize, GEMM_SMEM);
    cudaFuncSetAttribute((const void*)mma_gemm<2048, 1>,
                         cudaFuncAttributeMaxDynamicSharedMemorySize, GEMM_SMEM);
    cudaFuncSetAttribute((const void*)mma_gemm<2048, 0>,
                         cudaFuncAttributeMaxDynamicSharedMemorySize, GEMM_SMEM);
    cudaGetLastError();  // clear any benign error from in-capture attr set

    // bf16x3 operand preparation
    split_k<<<16384, 256>>>(hs,   gA, 8192 * 512, 0);                        // A' = hs
    split_k<<<12288, 256>>>(wqkv, gB, 6144 * 512, 1);                        // B' wqkv
    split_k<<<4096,  256>>>(wg,   gB + (size_t)6144 * 6144, 2048 * 512, 1);  // B' wg
    split_k<<<4096,  256>>>(wd,   gB + (size_t)8192 * 6144, 2048 * 512, 1);  // B' wd

    // qkv projection (tensor cores) + post-process
    mma_gemm<6144, 0><<<dim3(48, 64), 256, GEMM_SMEM>>>(gA, gB, gQKV);
    qkv_post_k<<<dim3(8192, 16), 128>>>(pos, qln, kln);

    // gate projection
    mma_gemm<2048, 1><<<dim3(16, 64), 256, GEMM_SMEM>>>(gA, gB + (size_t)6144 * 6144,
                                                        gQKV + (size_t)8192 * 2048);

    // chunked linear attention
    chunk_kv_k <<<dim3(NC, 32), 256, 65792>>>();
    scan_k     <<<dim3(32, 8), 256>>>();
    chunk_out_k<<<dim3(NC, 32), 256, 91140>>>();

    // group-norm * gate, then dense projection (tensor cores)
    norm_gate_k<<<dim3(8192, 16), 128>>>(gnw);
    split_k<<<16384, 256>>>(gQKV, gA, 8192 * 512, 0);                        // A' = og
    mma_gemm<2048, 0><<<dim3(16, 64), 256, GEMM_SMEM>>>(gA, gB + (size_t)8192 * 6144, out);
}